// round 4
// baseline (speedup 1.0000x reference)
#include <cuda_runtime.h>

#define DIM   128
#define DIM4  32   // float4s per row
#define NC    4

// Streaming load: gathers are ~guaranteed L1 misses (12.8MB tables, random
// index). no_allocate skips the L1 fill/allocate stage.
__device__ __forceinline__ float4 ldg_na(const float4* p) {
    float4 v;
    asm("ld.global.L1::no_allocate.v4.f32 {%0,%1,%2,%3}, [%4];"
        : "=f"(v.x), "=f"(v.y), "=f"(v.z), "=f"(v.w) : "l"(p));
    return v;
}

// Per-edge class-split reduction, stage 1: reduce a[4] over the lane&3
// sub-dimension. After this, each lane holds class c = ((lane&1)<<1)|((lane>>1)&1)
// summed over its 4-lane group. (Validated layout from round-2 kernel.)
__device__ __forceinline__ float reduce_stage1(const float a[4], int lane) {
    float x = (lane & 1) ? a[0] : a[2];
    float y = (lane & 1) ? a[1] : a[3];
    float rx = __shfl_xor_sync(0xffffffffu, x, 1);
    float ry = __shfl_xor_sync(0xffffffffu, y, 1);
    float A = ((lane & 1) ? a[2] : a[0]) + rx;
    float B = ((lane & 1) ? a[3] : a[1]) + ry;
    float z = (lane & 2) ? A : B;
    float rz = __shfl_xor_sync(0xffffffffu, z, 2);
    return ((lane & 2) ? B : A) + rz;
}

__global__ __launch_bounds__(256, 4) void edge_kernel(
    const float* __restrict__ rna,
    const float* __restrict__ prot,
    const int* __restrict__ ridx,
    const int* __restrict__ pidx,
    const float* __restrict__ wrel,
    const float* __restrict__ wcls,
    float* __restrict__ out,
    int E)
{
    const int lane   = threadIdx.x & 31;
    const int warp_g = blockIdx.x * (blockDim.x >> 5) + (threadIdx.x >> 5);
    const int nwarps = gridDim.x * (blockDim.x >> 5);

    // Fold weights inline, once per warp: Mc[j] = M[j][4*lane .. 4*lane+3],
    // M[j][d] = sum_c wcls[c*4+j] * wrel[c*DIM+d].
    const float4* wrv = reinterpret_cast<const float4*>(wrel);
    float4 wr[NC];
#pragma unroll
    for (int c = 0; c < NC; ++c) wr[c] = wrv[c * DIM4 + lane];
    float4 Mc[NC];
#pragma unroll
    for (int j = 0; j < NC; ++j) {
        float4 m = {0.f, 0.f, 0.f, 0.f};
#pragma unroll
        for (int c = 0; c < NC; ++c) {
            float w = wcls[c * NC + j];
            m.x += w * wr[c].x; m.y += w * wr[c].y;
            m.z += w * wr[c].z; m.w += w * wr[c].w;
        }
        Mc[j] = m;
    }

    const float4* rv = reinterpret_cast<const float4*>(rna);
    const float4* pv = reinterpret_cast<const float4*>(prot);

    const long long P = ((long long)E + 1) / 2;   // edge pairs

    for (long long q = warp_g; q < P; q += nwarps) {
        const int e0 = (int)(2 * q);
        const int e1 = e0 + 1;
        const bool v1 = (e1 < E);
        const int e1c = v1 ? e1 : e0;

        const int ri0 = ridx[e0], ri1 = ridx[e1c];
        const int pi0 = pidx[e0], pi1 = pidx[e1c];

        // 4 gathers in flight: each warp instruction covers one full 512B row.
        float4 r0 = ldg_na(rv + (long long)ri0 * DIM4 + lane);
        float4 p0 = ldg_na(pv + (long long)pi0 * DIM4 + lane);
        float4 r1 = ldg_na(rv + (long long)ri1 * DIM4 + lane);
        float4 p1 = ldg_na(pv + (long long)pi1 * DIM4 + lane);

        float4 rp0, rp1;
        rp0.x = r0.x * p0.x; rp0.y = r0.y * p0.y;
        rp0.z = r0.z * p0.z; rp0.w = r0.w * p0.w;
        rp1.x = r1.x * p1.x; rp1.y = r1.y * p1.y;
        rp1.z = r1.z * p1.z; rp1.w = r1.w * p1.w;

        float a0[NC], a1[NC];
#pragma unroll
        for (int j = 0; j < NC; ++j) {
            a0[j] = rp0.x * Mc[j].x + rp0.y * Mc[j].y
                  + rp0.z * Mc[j].z + rp0.w * Mc[j].w;
            a1[j] = rp1.x * Mc[j].x + rp1.y * Mc[j].y
                  + rp1.z * Mc[j].z + rp1.w * Mc[j].w;
        }

        // Stage 1 per edge (3 shfl each)
        float S0 = reduce_stage1(a0, lane);
        float S1 = reduce_stage1(a1, lane);

        // Merge the two edges on the xor-4 level (1 shfl): after this,
        // lanes with bit2=0 carry edge0, bit2=1 carry edge1.
        float t  = (lane & 4) ? S0 : S1;
        float rt = __shfl_xor_sync(0xffffffffu, t, 4);
        float U  = ((lane & 4) ? S1 : S0) + rt;

        // Fold remaining lane bits (2 shfl)
        U += __shfl_xor_sync(0xffffffffu, U, 8);
        U += __shfl_xor_sync(0xffffffffu, U, 16);

        // Lanes 0-7 write: lanes 0-3 -> edge0, 4-7 -> edge1; contiguous 32B.
        if (lane < 8) {
            const int e = e0 + ((lane >> 2) & 1);
            const int c = ((lane & 1) << 1) | ((lane >> 1) & 1);
            if (e < E) out[4 * e + c] = fmaxf(U, 0.f);
        }
    }
}

extern "C" void kernel_launch(void* const* d_in, const int* in_sizes, int n_in,
                              void* d_out, int out_size) {
    const float* rna  = (const float*)d_in[0];   // [20000,128] f32
    const float* prot = (const float*)d_in[1];   // [5000,128]  f32
    const int*   ridx = (const int*)d_in[2];     // [E] int32
    const int*   pidx = (const int*)d_in[3];     // [E] int32
    const float* wrel = (const float*)d_in[4];   // [4,128] f32
    const float* wcls = (const float*)d_in[5];   // [4,4]   f32
    float*       out  = (float*)d_out;           // [E,4]   f32

    const int E = in_sizes[2];
    const long long P = ((long long)E + 1) / 2;

    const int threads = 256;
    const int warps_per_block = threads / 32;
    long long blocks_needed = (P + warps_per_block - 1) / warps_per_block;
    int blocks = (int)(blocks_needed < 592 ? blocks_needed : 592); // 148 SMs x 4
    if (blocks < 1) blocks = 1;

    edge_kernel<<<blocks, threads>>>(rna, prot, ridx, pidx, wrel, wcls, out, E);
}

// round 6
// speedup vs baseline: 1.1921x; 1.1921x over previous
#include <cuda_runtime.h>

#define DIM   128
#define DIM4  32   // float4s per row
#define NC    4

// Folded weights: M[j][d] = sum_c Wc[c][j] * w_rel[c][d]
__device__ float g_M[NC * DIM];

__global__ void fold_weights_kernel(const float* __restrict__ w_rel,
                                    const float* __restrict__ w_cls) {
    int t = threadIdx.x;
    if (t < NC * DIM) {
        int j = t / DIM, d = t % DIM;
        float s = 0.f;
#pragma unroll
        for (int c = 0; c < NC; ++c)
            s += w_cls[c * NC + j] * w_rel[c * DIM + d];
        g_M[j * DIM + d] = s;
    }
}

// Streaming load: gathers are ~guaranteed L1 misses (12.8MB tables, random
// index). no_allocate skips the L1 fill/allocate stage.
__device__ __forceinline__ float4 ldg_na(const float4* p) {
    float4 v;
    asm("ld.global.L1::no_allocate.v4.f32 {%0,%1,%2,%3}, [%4];"
        : "=f"(v.x), "=f"(v.y), "=f"(v.z), "=f"(v.w) : "l"(p));
    return v;
}

// Class-split butterfly over the lane&3 sub-dimension (3 shfl). Afterwards,
// lane l holds class c = ((l&1)<<1)|((l>>1)&1) summed over its 4-lane group.
__device__ __forceinline__ float reduce_stage1(const float a[4], int lane) {
    float x = (lane & 1) ? a[0] : a[2];
    float y = (lane & 1) ? a[1] : a[3];
    float rx = __shfl_xor_sync(0xffffffffu, x, 1);
    float ry = __shfl_xor_sync(0xffffffffu, y, 1);
    float A = ((lane & 1) ? a[2] : a[0]) + rx;
    float B = ((lane & 1) ? a[3] : a[1]) + ry;
    float z = (lane & 2) ? A : B;
    float rz = __shfl_xor_sync(0xffffffffu, z, 2);
    return ((lane & 2) ? B : A) + rz;
}

// 16 lanes per edge; each warp handles 4 edges: halfwarp `sub` owns edges
// 4w+sub and 4w+2+sub. Lane h=lane&15 owns float4 chunks h and h+16 of each
// row, so the folded-weight slice is 8 float4 = 32 regs: fully resident.
__global__ __launch_bounds__(256) void edge_kernel(
    const float* __restrict__ rna,
    const float* __restrict__ prot,
    const int* __restrict__ ridx,
    const int* __restrict__ pidx,
    float* __restrict__ out,
    int E)
{
    const int lane = threadIdx.x & 31;
    const int h    = lane & 15;
    const int sub  = lane >> 4;
    const int w    = (blockIdx.x * blockDim.x + threadIdx.x) >> 5;

    // Resident folded weights: Mc0[j] = M[j][4h..4h+3], Mc1[j] = M[j][64+4h..]
    const float4* Mv = reinterpret_cast<const float4*>(g_M);
    float4 Mc0[NC], Mc1[NC];
#pragma unroll
    for (int j = 0; j < NC; ++j) {
        Mc0[j] = Mv[j * DIM4 + h];
        Mc1[j] = Mv[j * DIM4 + 16 + h];
    }

    const int e0 = 4 * w + sub;      // first edge of this halfwarp
    const int e1 = e0 + 2;           // second edge
    const int ee0 = (e0 < E) ? e0 : (E > 0 ? E - 1 : 0);
    const int ee1 = (e1 < E) ? e1 : (E > 0 ? E - 1 : 0);

    const int ri0 = ridx[ee0], pi0 = pidx[ee0];
    const int ri1 = ridx[ee1], pi1 = pidx[ee1];

    const float4* rv = reinterpret_cast<const float4*>(rna);
    const float4* pv = reinterpret_cast<const float4*>(prot);

    // 8 gathers in flight per lane. Each warp load instruction touches
    // 2 halfwarps x 256B contiguous = 4 cache lines: perfect coalescing.
    const long long rb0 = (long long)ri0 * DIM4;
    const long long pb0 = (long long)pi0 * DIM4;
    const long long rb1 = (long long)ri1 * DIM4;
    const long long pb1 = (long long)pi1 * DIM4;

    float4 r00 = ldg_na(rv + rb0 + h);
    float4 r01 = ldg_na(rv + rb0 + 16 + h);
    float4 p00 = ldg_na(pv + pb0 + h);
    float4 p01 = ldg_na(pv + pb0 + 16 + h);
    float4 r10 = ldg_na(rv + rb1 + h);
    float4 r11 = ldg_na(rv + rb1 + 16 + h);
    float4 p10 = ldg_na(pv + pb1 + h);
    float4 p11 = ldg_na(pv + pb1 + 16 + h);

    float4 q00, q01, q10, q11;
    q00.x = r00.x * p00.x; q00.y = r00.y * p00.y;
    q00.z = r00.z * p00.z; q00.w = r00.w * p00.w;
    q01.x = r01.x * p01.x; q01.y = r01.y * p01.y;
    q01.z = r01.z * p01.z; q01.w = r01.w * p01.w;
    q10.x = r10.x * p10.x; q10.y = r10.y * p10.y;
    q10.z = r10.z * p10.z; q10.w = r10.w * p10.w;
    q11.x = r11.x * p11.x; q11.y = r11.y * p11.y;
    q11.z = r11.z * p11.z; q11.w = r11.w * p11.w;

    float a0[NC], a1[NC];
#pragma unroll
    for (int j = 0; j < NC; ++j) {
        a0[j] = q00.x * Mc0[j].x + q00.y * Mc0[j].y
              + q00.z * Mc0[j].z + q00.w * Mc0[j].w
              + q01.x * Mc1[j].x + q01.y * Mc1[j].y
              + q01.z * Mc1[j].z + q01.w * Mc1[j].w;
        a1[j] = q10.x * Mc0[j].x + q10.y * Mc0[j].y
              + q10.z * Mc0[j].z + q10.w * Mc0[j].w
              + q11.x * Mc1[j].x + q11.y * Mc1[j].y
              + q11.z * Mc1[j].z + q11.w * Mc1[j].w;
    }

    // Per-edge reduction: class-split (3 shfl) + fold 16-lane half (2 shfl).
    float S0 = reduce_stage1(a0, lane);
    S0 += __shfl_xor_sync(0xffffffffu, S0, 4);
    S0 += __shfl_xor_sync(0xffffffffu, S0, 8);
    float S1 = reduce_stage1(a1, lane);
    S1 += __shfl_xor_sync(0xffffffffu, S1, 4);
    S1 += __shfl_xor_sync(0xffffffffu, S1, 8);

    // Lanes h<4 of each halfwarp write their class for each edge.
    if (h < 4) {
        const int c = ((h & 1) << 1) | ((h >> 1) & 1);
        if (e0 < E) out[4 * e0 + c] = fmaxf(S0, 0.f);
        if (e1 < E) out[4 * e1 + c] = fmaxf(S1, 0.f);
    }
}

extern "C" void kernel_launch(void* const* d_in, const int* in_sizes, int n_in,
                              void* d_out, int out_size) {
    const float* rna  = (const float*)d_in[0];   // [20000,128] f32
    const float* prot = (const float*)d_in[1];   // [5000,128]  f32
    const int*   ridx = (const int*)d_in[2];     // [E] int32
    const int*   pidx = (const int*)d_in[3];     // [E] int32
    const float* wrel = (const float*)d_in[4];   // [4,128] f32
    const float* wcls = (const float*)d_in[5];   // [4,4]   f32
    float*       out  = (float*)d_out;           // [E,4]   f32

    const int E = in_sizes[2];

    fold_weights_kernel<<<1, NC * DIM>>>(wrel, wcls);

    // One warp per 4 edges, 256 threads (8 warps) per block.
    const long long warps  = ((long long)E + 3) / 4;
    const long long blocks = (warps + 7) / 8;
    edge_kernel<<<(int)blocks, 256>>>(rna, prot, ridx, pidx, out, E);
}